// round 13
// baseline (speedup 1.0000x reference)
#include <cuda_runtime.h>
#include <cuda_fp16.h>
#include <cstdint>

#define BATCH    256
#define IN_DIM   512
#define OUT_DIM  512
#define NWORK    512
#define TOPK     154

// ------------------- persistent device scratch (no runtime allocation) -------------------
__device__ int   d_count[NWORK];                        // tokens per expert
__device__ int   d_tok[NWORK * 256];                    // token id per (expert, row)
__device__ float d_wt [NWORK * 256];                    // gate weight per (expert, row)
__device__ int   d_dst[NWORK * 256];                    // staging row (= b*TOPK + slot)
__device__ int   d_tokcnt[BATCH];                       // slot counter per token
__device__ float d_ystage[BATCH * TOPK * OUT_DIM];      // 77 MB staging: [token, slot, out]

// ------------------- helpers (baseline compute_103 PTX only) -------------------
__device__ __forceinline__ uint32_t smem_u32(const void* p) {
    uint32_t a;
    asm("{ .reg .u64 t; cvta.to.shared.u64 t, %1; cvt.u32.u64 %0, t; }" : "=r"(a) : "l"(p));
    return a;
}
#define SWZ(o) ((o) ^ (((o) >> 3) & 0x70))

__device__ __forceinline__ void ldm_x4(uint32_t* r, uint32_t addr) {
    asm volatile("ldmatrix.sync.aligned.m8n8.x4.shared.b16 {%0,%1,%2,%3}, [%4];"
                 : "=r"(r[0]), "=r"(r[1]), "=r"(r[2]), "=r"(r[3]) : "r"(addr));
}

__device__ __forceinline__ void mma_fp16(float* d, const uint32_t* a, const uint32_t* b) {
    asm volatile("mma.sync.aligned.m16n8k16.row.col.f32.f16.f16.f32 "
                 "{%0,%1,%2,%3}, {%4,%5,%6,%7}, {%8,%9}, {%0,%1,%2,%3};"
                 : "+f"(d[0]), "+f"(d[1]), "+f"(d[2]), "+f"(d[3])
                 : "r"(a[0]), "r"(a[1]), "r"(a[2]), "r"(a[3]), "r"(b[0]), "r"(b[1]));
}

__device__ __forceinline__ void sts128(uint32_t addr, uint4 v) {
    asm volatile("st.shared.v4.b32 [%0], {%1, %2, %3, %4};"
                 :: "r"(addr), "r"(v.x), "r"(v.y), "r"(v.z), "r"(v.w) : "memory");
}

__device__ __forceinline__ uint32_t pack_h2(float a, float b) {
    __half2 h = __floats2half2_rn(a, b);          // .x (low half) = a
    return *reinterpret_cast<uint32_t*>(&h);
}

// 2x float4 -> fp16x8 (single-rounded plane)
__device__ __forceinline__ uint4 cvt8_single(float4 v0, float4 v1) {
    return make_uint4(pack_h2(v0.x, v0.y), pack_h2(v0.z, v0.w),
                      pack_h2(v1.x, v1.y), pack_h2(v1.z, v1.w));
}

// ------------------- kernel 0: zero counters -------------------
__global__ void zero_kernel() {
    int i = threadIdx.x;
    if (i < NWORK) d_count[i] = 0;
    if (i < BATCH) d_tokcnt[i] = 0;
}

// ------------------- kernel 1: router -------------------
__global__ void __launch_bounds__(512) router_kernel(const float* __restrict__ x,
                                                     const float* __restrict__ gw,
                                                     const float* __restrict__ gb) {
    __shared__ __align__(16) float sx[4][IN_DIM];
    __shared__ float sred[512];
    const int e  = threadIdx.x;
    const int b0 = blockIdx.x * 4;

    for (int i = e; i < 4 * IN_DIM; i += 512) sx[i >> 9][i & 511] = x[b0 * IN_DIM + i];
    __syncthreads();

    float bias = gb[e];
    float acc[4] = {bias, bias, bias, bias};
    const float4* g4 = (const float4*)(gw + (size_t)e * IN_DIM);
#pragma unroll 4
    for (int k = 0; k < IN_DIM / 4; k++) {
        float4 g = g4[k];
#pragma unroll
        for (int t = 0; t < 4; t++) {
            float4 xv = ((const float4*)sx[t])[k];
            acc[t] += g.x * xv.x + g.y * xv.y + g.z * xv.z + g.w * xv.w;
        }
    }

    for (int t = 0; t < 4; t++) {
        const int b = b0 + t;
        const float l = acc[t];
        uint32_t u = __float_as_uint(l);
        u = (u & 0x80000000u) ? ~u : (u | 0x80000000u);   // order-preserving map

        uint32_t res = 0;                                  // K-th largest threshold
        for (int bit = 31; bit >= 0; bit--) {
            uint32_t cand = res | (1u << bit);
            int c = __syncthreads_count(u >= cand);
            if (c >= TOPK) res = cand;
        }
        const bool sel = (u >= res);

        sred[e] = l;
        __syncthreads();
        for (int s = 256; s; s >>= 1) { if (e < s) sred[e] = fmaxf(sred[e], sred[e + s]); __syncthreads(); }
        const float lmax = sred[0];
        __syncthreads();

        const float ex = sel ? __expf(l - lmax) : 0.f;
        sred[e] = ex;
        __syncthreads();
        for (int s = 256; s; s >>= 1) { if (e < s) sred[e] += sred[e + s]; __syncthreads(); }
        const float wsum = sred[0];
        __syncthreads();

        if (sel) {
            float w = ex / wsum;
            int r = atomicAdd(&d_count[e], 1);
            int j = atomicAdd(&d_tokcnt[b], 1);
            if (r < 256 && j < TOPK) {
                d_tok[e * 256 + r] = b;
                d_wt [e * 256 + r] = w;
                d_dst[e * 256 + r] = b * TOPK + j;
            }
        }
        __syncthreads();
    }
}

// ------------------- kernel 2: grouped GEMM (HMMA fp16, M128xN64 tiles, 3 CTAs/SM) -------------------
// grid (expert 512, n-eighth 8, m-chunk 2), 256 thr.
// Warp w = M-strip [16w,16w+16) x full N64. A = x fp16 (no weight); w applied in epilogue.
#define SM_TOK   0
#define SM_WT    512
#define SM_DST   1024
#define SM_BUF   2048
#define BUF_SZ   24576           /* A 16K + B 8K */
#define A_OFF    0
#define B_OFF    16384
#define SMEM_BYTES (2048 + 2 * BUF_SZ)   /* 51200 B */

__global__ void __launch_bounds__(256, 3)
moe_gemm(const float* __restrict__ x, const float* __restrict__ tiles) {
    extern __shared__ char smem[];
    const int e  = blockIdx.x;
    const int nq = blockIdx.y;          // N-eighth: cols [nq*64, nq*64+64)
    const int mc = blockIdx.z;
    const int cnt  = d_count[e];
    const int rows = min(128, cnt - mc * 128);
    if (rows <= 0) return;

    const uint32_t sb  = smem_u32(smem);
    const int tid = threadIdx.x, wid = tid >> 5, lid = tid & 31;
    const int m0 = wid * 16;

    if (tid < 128) {
        int r = tid;
        bool valid = r < rows;
        int idx = e * 256 + mc * 128 + r;
        ((int*)  (smem + SM_TOK))[r] = valid ? d_tok[idx] : 0;
        ((float*)(smem + SM_WT ))[r] = valid ? d_wt [idx] : 0.f;
        ((int*)  (smem + SM_DST))[r] = valid ? d_dst[idx] : 0;
    }
    __syncthreads();

    // ldmatrix lane address components (validated in R10-R12)
    const int ar  = (lid & 7) + ((lid >> 3) & 1) * 8;   // A: row within strip
    const int akb = ((lid >> 4) & 1) * 16;              // A: k-byte offset
    const int br  = (lid & 7) + ((lid >> 4) & 1) * 8;   // B: n within 16-group
    const int bkb = ((lid >> 3) & 1) * 16;              // B: k-byte offset

    float acc[8][4];
#pragma unroll
    for (int t = 0; t < 8; t++)
#pragma unroll
        for (int j = 0; j < 4; j++) acc[t][j] = 0.f;

    const float* tbase = tiles + ((size_t)e * OUT_DIM + nq * 64) * IN_DIM;

    // fill-role indices
    const int frB = tid >> 2, fgB = tid & 3;   // B: row 0..63, 16-col group 0..3
    const int frA = tid >> 1, fgA = tid & 1;   // A: row 0..127, 32-col group 0..1

    float4 pf[4];                               // B prefetch registers (one row segment)

    // ---- B: issue 4 LDG.128 for chunk kc into pf ----
    auto loadB = [&](int kc) {
        const float4* p = (const float4*)(tbase + (size_t)frB * IN_DIM + kc * 64 + fgB * 16);
#pragma unroll
        for (int j = 0; j < 4; j++) pf[j] = p[j];
    };
    // ---- B: convert prefetched regs into buffer ----
    auto storeB = [&](uint32_t bufb) {
        uint32_t base = (uint32_t)(frB * 128 + fgB * 32);
        sts128(bufb + B_OFF + SWZ(base),      cvt8_single(pf[0], pf[1]));
        sts128(bufb + B_OFF + SWZ(base + 16), cvt8_single(pf[2], pf[3]));
    };
    // ---- A: gather + convert + store (x is L2-resident) ----
    auto fillA = [&](int kc, uint32_t bufb) {
        int tok = ((int*)(smem + SM_TOK))[frA];
        const float4* p = (const float4*)(x + (size_t)tok * IN_DIM + kc * 64 + fgA * 32);
        float4 v0 = p[0], v1 = p[1], v2 = p[2], v3 = p[3];
        float4 v4 = p[4], v5 = p[5], v6 = p[6], v7 = p[7];
        uint32_t base = (uint32_t)(frA * 128 + fgA * 64);
        sts128(bufb + A_OFF + SWZ(base),      cvt8_single(v0, v1));
        sts128(bufb + A_OFF + SWZ(base + 16), cvt8_single(v2, v3));
        sts128(bufb + A_OFF + SWZ(base + 32), cvt8_single(v4, v5));
        sts128(bufb + A_OFF + SWZ(base + 48), cvt8_single(v6, v7));
    };

    // prologue: stage chunk 0
    loadB(0);
    storeB(sb + SM_BUF);
    fillA(0, sb + SM_BUF);
    __syncthreads();

    for (int kc = 0; kc < 8; kc++) {
        const uint32_t cur = sb + SM_BUF + (uint32_t)(kc & 1) * BUF_SZ;

        if (kc < 7) loadB(kc + 1);             // DRAM LDGs in flight across the MMA phase

        if (m0 < rows) {                       // M-skip: warps past `rows` act as producers only
#pragma unroll
            for (int ks = 0; ks < 4; ks++) {
                uint32_t a[4];
                uint32_t aoff = SWZ((uint32_t)((m0 + ar) * 128 + 32 * ks + akb));
                ldm_x4(a, cur + A_OFF + aoff);
#pragma unroll
                for (int np = 0; np < 4; np++) {
                    uint32_t b[4];
                    uint32_t boff = SWZ((uint32_t)((np * 16 + br) * 128 + 32 * ks + bkb));
                    ldm_x4(b, cur + B_OFF + boff);
                    mma_fp16(acc[2 * np],     a, b);
                    mma_fp16(acc[2 * np + 1], a, b + 2);
                }
            }
        }

        if (kc < 7) {
            const uint32_t nxt = sb + SM_BUF + (uint32_t)((kc + 1) & 1) * BUF_SZ;
            storeB(nxt);
            fillA(kc + 1, nxt);
            __syncthreads();                   // one barrier per chunk
        }
    }

    // epilogue: rows mA = m0 + lid/4, mB = mA + 8; apply gate weight here
    if (m0 < rows) {
        const int mA = m0 + (lid >> 2);
        const int mB = mA + 8;
        const bool vA = mA < rows, vB = mB < rows;
        const int dA = vA ? ((int*)(smem + SM_DST))[mA] : 0;
        const int dB = vB ? ((int*)(smem + SM_DST))[mB] : 0;
        const float wA = vA ? ((float*)(smem + SM_WT))[mA] : 0.f;
        const float wB = vB ? ((float*)(smem + SM_WT))[mB] : 0.f;
        float* oA = d_ystage + (size_t)dA * OUT_DIM + nq * 64;
        float* oB = d_ystage + (size_t)dB * OUT_DIM + nq * 64;
        const int nb = 2 * (lid & 3);
#pragma unroll
        for (int t = 0; t < 8; t++) {
            int n = t * 8 + nb;
            if (vA) *(float2*)(oA + n) = make_float2(wA * acc[t][0], wA * acc[t][1]);
            if (vB) *(float2*)(oB + n) = make_float2(wB * acc[t][2], wB * acc[t][3]);
        }
    }
}

// ------------------- kernel 3: per-token reduction over 154 staged rows -------------------
__global__ void __launch_bounds__(256) reduce_kernel(float* __restrict__ out) {
    const int b    = blockIdx.x >> 1;
    const int half = blockIdx.x & 1;
    const int c    = half * 256 + threadIdx.x;
    const float* base = d_ystage + (size_t)b * TOPK * OUT_DIM + c;
    float a0 = 0.f, a1 = 0.f, a2 = 0.f, a3 = 0.f;
    float a4 = 0.f, a5 = 0.f, a6 = 0.f, a7 = 0.f;
    int j = 0;
    for (; j + 8 <= TOPK; j += 8) {            // 8-way MLP
        a0 += base[(size_t)(j + 0) * OUT_DIM];
        a1 += base[(size_t)(j + 1) * OUT_DIM];
        a2 += base[(size_t)(j + 2) * OUT_DIM];
        a3 += base[(size_t)(j + 3) * OUT_DIM];
        a4 += base[(size_t)(j + 4) * OUT_DIM];
        a5 += base[(size_t)(j + 5) * OUT_DIM];
        a6 += base[(size_t)(j + 6) * OUT_DIM];
        a7 += base[(size_t)(j + 7) * OUT_DIM];
    }
    for (; j < TOPK; j++) a0 += base[(size_t)j * OUT_DIM];
    out[b * OUT_DIM + c] = ((a0 + a1) + (a2 + a3)) + ((a4 + a5) + (a6 + a7));
}

// ------------------- launcher -------------------
extern "C" void kernel_launch(void* const* d_in, const int* in_sizes, int n_in,
                              void* d_out, int out_size) {
    const float* x     = (const float*)d_in[0];
    const float* gw    = (const float*)d_in[1];
    const float* gb    = (const float*)d_in[2];
    const float* tiles = (const float*)d_in[3];
    float* out = (float*)d_out;

    zero_kernel<<<1, 512>>>();
    router_kernel<<<BATCH / 4, 512>>>(x, gw, gb);
    cudaFuncSetAttribute(moe_gemm, cudaFuncAttributeMaxDynamicSharedMemorySize, SMEM_BYTES);
    moe_gemm<<<dim3(NWORK, 8, 2), 256, SMEM_BYTES>>>(x, tiles);
    reduce_kernel<<<BATCH * 2, 256>>>(out);
}

// round 15
// speedup vs baseline: 1.0135x; 1.0135x over previous
#include <cuda_runtime.h>
#include <cuda_fp16.h>
#include <cstdint>

#define BATCH    256
#define IN_DIM   512
#define OUT_DIM  512
#define NWORK    512
#define TOPK     154

// ------------------- persistent device scratch (no runtime allocation) -------------------
__device__ int   d_count[NWORK];                        // tokens per expert
__device__ int   d_tok[NWORK * 256];                    // token id per (expert, row)
__device__ float d_wt [NWORK * 256];                    // gate weight per (expert, row)
__device__ int   d_dst[NWORK * 256];                    // staging row (= b*TOPK + slot)
__device__ int   d_tokcnt[BATCH];                       // slot counter per token
__device__ float d_ystage[BATCH * TOPK * OUT_DIM];      // 77 MB staging: [token, slot, out]

// ------------------- helpers (baseline compute_103 PTX only) -------------------
__device__ __forceinline__ uint32_t smem_u32(const void* p) {
    uint32_t a;
    asm("{ .reg .u64 t; cvta.to.shared.u64 t, %1; cvt.u32.u64 %0, t; }" : "=r"(a) : "l"(p));
    return a;
}
#define SWZ(o) ((o) ^ (((o) >> 3) & 0x70))

__device__ __forceinline__ void ldm_x4(uint32_t* r, uint32_t addr) {
    asm volatile("ldmatrix.sync.aligned.m8n8.x4.shared.b16 {%0,%1,%2,%3}, [%4];"
                 : "=r"(r[0]), "=r"(r[1]), "=r"(r[2]), "=r"(r[3]) : "r"(addr));
}

__device__ __forceinline__ void mma_fp16(float* d, const uint32_t* a, const uint32_t* b) {
    asm volatile("mma.sync.aligned.m16n8k16.row.col.f32.f16.f16.f32 "
                 "{%0,%1,%2,%3}, {%4,%5,%6,%7}, {%8,%9}, {%0,%1,%2,%3};"
                 : "+f"(d[0]), "+f"(d[1]), "+f"(d[2]), "+f"(d[3])
                 : "r"(a[0]), "r"(a[1]), "r"(a[2]), "r"(a[3]), "r"(b[0]), "r"(b[1]));
}

__device__ __forceinline__ void sts128(uint32_t addr, uint4 v) {
    asm volatile("st.shared.v4.b32 [%0], {%1, %2, %3, %4};"
                 :: "r"(addr), "r"(v.x), "r"(v.y), "r"(v.z), "r"(v.w) : "memory");
}
__device__ __forceinline__ void sts64(uint32_t addr, uint32_t x, uint32_t y) {
    asm volatile("st.shared.v2.b32 [%0], {%1, %2};" :: "r"(addr), "r"(x), "r"(y) : "memory");
}

__device__ __forceinline__ void cp_async16(uint32_t smem_addr, const void* gptr) {
    asm volatile("cp.async.cg.shared.global [%0], [%1], 16;"
                 :: "r"(smem_addr), "l"(gptr) : "memory");
}
__device__ __forceinline__ void cp_commit()  { asm volatile("cp.async.commit_group;" ::: "memory"); }
__device__ __forceinline__ void cp_wait0()   { asm volatile("cp.async.wait_group 0;" ::: "memory"); }

__device__ __forceinline__ uint32_t pack_h2(float a, float b) {
    __half2 h = __floats2half2_rn(a, b);          // .x (low half) = a
    return *reinterpret_cast<uint32_t*>(&h);
}
__device__ __forceinline__ uint4 cvt8_single(float4 v0, float4 v1) {
    return make_uint4(pack_h2(v0.x, v0.y), pack_h2(v0.z, v0.w),
                      pack_h2(v1.x, v1.y), pack_h2(v1.z, v1.w));
}

// ------------------- kernel 0: zero counters -------------------
__global__ void zero_kernel() {
    int i = threadIdx.x;
    if (i < NWORK) d_count[i] = 0;
    if (i < BATCH) d_tokcnt[i] = 0;
}

// ------------------- kernel 1: router -------------------
__global__ void __launch_bounds__(512) router_kernel(const float* __restrict__ x,
                                                     const float* __restrict__ gw,
                                                     const float* __restrict__ gb) {
    __shared__ __align__(16) float sx[4][IN_DIM];
    __shared__ float sred[512];
    const int e  = threadIdx.x;
    const int b0 = blockIdx.x * 4;

    for (int i = e; i < 4 * IN_DIM; i += 512) sx[i >> 9][i & 511] = x[b0 * IN_DIM + i];
    __syncthreads();

    float bias = gb[e];
    float acc[4] = {bias, bias, bias, bias};
    const float4* g4 = (const float4*)(gw + (size_t)e * IN_DIM);
#pragma unroll 4
    for (int k = 0; k < IN_DIM / 4; k++) {
        float4 g = g4[k];
#pragma unroll
        for (int t = 0; t < 4; t++) {
            float4 xv = ((const float4*)sx[t])[k];
            acc[t] += g.x * xv.x + g.y * xv.y + g.z * xv.z + g.w * xv.w;
        }
    }

    for (int t = 0; t < 4; t++) {
        const int b = b0 + t;
        const float l = acc[t];
        uint32_t u = __float_as_uint(l);
        u = (u & 0x80000000u) ? ~u : (u | 0x80000000u);   // order-preserving map

        uint32_t res = 0;                                  // K-th largest threshold
        for (int bit = 31; bit >= 0; bit--) {
            uint32_t cand = res | (1u << bit);
            int c = __syncthreads_count(u >= cand);
            if (c >= TOPK) res = cand;
        }
        const bool sel = (u >= res);

        sred[e] = l;
        __syncthreads();
        for (int s = 256; s; s >>= 1) { if (e < s) sred[e] = fmaxf(sred[e], sred[e + s]); __syncthreads(); }
        const float lmax = sred[0];
        __syncthreads();

        const float ex = sel ? __expf(l - lmax) : 0.f;
        sred[e] = ex;
        __syncthreads();
        for (int s = 256; s; s >>= 1) { if (e < s) sred[e] += sred[e + s]; __syncthreads(); }
        const float wsum = sred[0];
        __syncthreads();

        if (sel) {
            float w = ex / wsum;
            int r = atomicAdd(&d_count[e], 1);
            int j = atomicAdd(&d_tokcnt[b], 1);
            if (r < 256 && j < TOPK) {
                d_tok[e * 256 + r] = b;
                d_wt [e * 256 + r] = w;
                d_dst[e * 256 + r] = b * TOPK + j;
            }
        }
        __syncthreads();
    }
}

// ------------------- kernel 2: grouped GEMM (HMMA fp16, cp.async B stage, warps 4x2) -------------------
// grid (expert 512, n-quarter 4, m-chunk 2), 256 thr, 2 CTAs/SM.
// Warp wid: m-strip (wid>>1)*32, n-half (wid&1)*64. A = x fp16; gate weight in epilogue.
// cp.async unit mapping == storeB read mapping (thread-private), so per-thread
// cp.async.wait_group is the only ordering needed for the stage buffer.
#define SM_TOK   0
#define SM_WT    512
#define SM_DST   1024
#define SM_BUF   2048
#define BUF_SZ   32768           /* A 16K + B 16K fp16 */
#define A_OFF    0
#define B_OFF    16384
#define SM_STAGE (2048 + 2 * BUF_SZ)        /* 32 KB raw f32 B stage */
#define SMEM_BYTES (SM_STAGE + 32768)       /* 100352 B */

__global__ void __launch_bounds__(256, 2)
moe_gemm(const float* __restrict__ x, const float* __restrict__ tiles) {
    extern __shared__ char smem[];
    const int e  = blockIdx.x;
    const int nq = blockIdx.y;          // N-quarter: cols [nq*128, nq*128+128)
    const int mc = blockIdx.z;
    const int cnt  = d_count[e];
    const int rows = min(128, cnt - mc * 128);
    if (rows <= 0) return;

    const uint32_t sb  = smem_u32(smem);
    const int tid = threadIdx.x, wid = tid >> 5, lid = tid & 31;
    const int m0 = (wid >> 1) * 32;     // warp m-strip
    const int n0 = (wid & 1) * 64;      // warp n-half

    if (tid < 128) {
        int r = tid;
        bool valid = r < rows;
        int idx = e * 256 + mc * 128 + r;
        ((int*)  (smem + SM_TOK))[r] = valid ? d_tok[idx] : 0;
        ((float*)(smem + SM_WT ))[r] = valid ? d_wt [idx] : 0.f;
        ((int*)  (smem + SM_DST))[r] = valid ? d_dst[idx] : 0;
    }
    __syncthreads();

    // ldmatrix lane address components (validated R10-R12)
    const int ar  = (lid & 7) + ((lid >> 3) & 1) * 8;   // A: row within 16-tile
    const int akb = ((lid >> 4) & 1) * 16;              // A: k-byte offset
    const int br  = (lid & 7) + ((lid >> 4) & 1) * 8;   // B: n within 16-group
    const int bkb = ((lid >> 3) & 1) * 16;              // B: k-byte offset

    float acc[2][8][4];
#pragma unroll
    for (int mt = 0; mt < 2; mt++)
#pragma unroll
        for (int t = 0; t < 8; t++)
#pragma unroll
            for (int j = 0; j < 4; j++) acc[mt][t][j] = 0.f;

    const float* tbase = tiles + ((size_t)e * OUT_DIM + nq * 128) * IN_DIM;
    const uint32_t stage = sb + SM_STAGE;

    // ---- B: async copy chunk kc (128 rows x 64 f32 = 32KB) into raw stage ----
    // unit idx = tid + j*256  (matches storeB's read mapping: thread-private data)
    auto loadB = [&](int kc) {
#pragma unroll
        for (int j = 0; j < 8; j++) {
            int idx = tid + j * 256;                     // 16B unit
            int row = idx >> 4, seg = idx & 15;
            cp_async16(stage + (uint32_t)idx * 16,
                       tbase + (size_t)row * IN_DIM + kc * 64 + seg * 4);
        }
        cp_commit();
    };
    // ---- B: convert stage -> fp16 buffer (reads ONLY this thread's own units) ----
    auto storeB = [&](uint32_t bufb) {
#pragma unroll
        for (int j = 0; j < 8; j++) {
            float4 v = *(const float4*)(smem + SM_STAGE + tid * 16 + j * 4096);  // unit tid + j*256
            int row = j * 16 + (tid >> 4);               // B row 0..127
            int cb  = (tid & 15) * 8;                    // byte col (4 floats -> 8B fp16)
            sts64(bufb + B_OFF + SWZ((uint32_t)(row * 128 + cb)),
                  pack_h2(v.x, v.y), pack_h2(v.z, v.w));
        }
    };
    // ---- A: gather + convert + store (x is L2-resident) ----
    auto fillA = [&](int kc, uint32_t bufb) {
        int r = tid >> 1, g = tid & 1;
        int tok = ((int*)(smem + SM_TOK))[r];
        const float4* p = (const float4*)(x + (size_t)tok * IN_DIM + kc * 64 + g * 32);
        float4 v0 = p[0], v1 = p[1], v2 = p[2], v3 = p[3];
        float4 v4 = p[4], v5 = p[5], v6 = p[6], v7 = p[7];
        uint32_t base = (uint32_t)(r * 128 + g * 64);
        sts128(bufb + A_OFF + SWZ(base),      cvt8_single(v0, v1));
        sts128(bufb + A_OFF + SWZ(base + 16), cvt8_single(v2, v3));
        sts128(bufb + A_OFF + SWZ(base + 32), cvt8_single(v4, v5));
        sts128(bufb + A_OFF + SWZ(base + 48), cvt8_single(v6, v7));
    };

    // prologue: stage chunk 0
    loadB(0);
    fillA(0, sb + SM_BUF);
    cp_wait0();
    storeB(sb + SM_BUF);
    __syncthreads();

    for (int kc = 0; kc < 8; kc++) {
        const uint32_t cur = sb + SM_BUF + (uint32_t)(kc & 1) * BUF_SZ;

        if (kc < 7) loadB(kc + 1);             // async: lands during MMA phase

        if (m0 < rows) {                       // M-skip (32-row strips)
#pragma unroll
            for (int ks = 0; ks < 4; ks++) {
                uint32_t a0[4], a1[4];
                ldm_x4(a0, cur + A_OFF + SWZ((uint32_t)((m0 + ar) * 128 + 32 * ks + akb)));
                ldm_x4(a1, cur + A_OFF + SWZ((uint32_t)((m0 + 16 + ar) * 128 + 32 * ks + akb)));
#pragma unroll
                for (int np = 0; np < 4; np++) {
                    uint32_t b[4];
                    ldm_x4(b, cur + B_OFF + SWZ((uint32_t)((n0 + np * 16 + br) * 128 + 32 * ks + bkb)));
                    mma_fp16(acc[0][2 * np],     a0, b);
                    mma_fp16(acc[1][2 * np],     a1, b);
                    mma_fp16(acc[0][2 * np + 1], a0, b + 2);
                    mma_fp16(acc[1][2 * np + 1], a1, b + 2);
                }
            }
        }

        if (kc < 7) {
            const uint32_t nxt = sb + SM_BUF + (uint32_t)((kc + 1) & 1) * BUF_SZ;
            fillA(kc + 1, nxt);
            cp_wait0();
            storeB(nxt);
            __syncthreads();                   // one barrier per chunk
        }
    }

    // epilogue: rows m0+16*mt+lid/4 (+8); cols n0 + t*8 + 2*(lid&3); apply gate weight
    if (m0 < rows) {
#pragma unroll
        for (int mt = 0; mt < 2; mt++) {
            const int mA = m0 + 16 * mt + (lid >> 2);
            const int mB = mA + 8;
            const bool vA = mA < rows, vB = mB < rows;
            const int dA = vA ? ((int*)(smem + SM_DST))[mA] : 0;
            const int dB = vB ? ((int*)(smem + SM_DST))[mB] : 0;
            const float wA = vA ? ((float*)(smem + SM_WT))[mA] : 0.f;
            const float wB = vB ? ((float*)(smem + SM_WT))[mB] : 0.f;
            float* oA = d_ystage + (size_t)dA * OUT_DIM + nq * 128 + n0;
            float* oB = d_ystage + (size_t)dB * OUT_DIM + nq * 128 + n0;
            const int nb = 2 * (lid & 3);
#pragma unroll
            for (int t = 0; t < 8; t++) {
                int n = t * 8 + nb;
                if (vA) *(float2*)(oA + n) = make_float2(wA * acc[mt][t][0], wA * acc[mt][t][1]);
                if (vB) *(float2*)(oB + n) = make_float2(wB * acc[mt][t][2], wB * acc[mt][t][3]);
            }
        }
    }
}

// ------------------- kernel 3: per-token reduction over 154 staged rows -------------------
__global__ void __launch_bounds__(256) reduce_kernel(float* __restrict__ out) {
    const int b    = blockIdx.x >> 1;
    const int half = blockIdx.x & 1;
    const int c    = half * 256 + threadIdx.x;
    const float* base = d_ystage + (size_t)b * TOPK * OUT_DIM + c;
    float a0 = 0.f, a1 = 0.f, a2 = 0.f, a3 = 0.f;
    float a4 = 0.f, a5 = 0.f, a6 = 0.f, a7 = 0.f;
    int j = 0;
    for (; j + 8 <= TOPK; j += 8) {            // 8-way MLP
        a0 += base[(size_t)(j + 0) * OUT_DIM];
        a1 += base[(size_t)(j + 1) * OUT_DIM];
        a2 += base[(size_t)(j + 2) * OUT_DIM];
        a3 += base[(size_t)(j + 3) * OUT_DIM];
        a4 += base[(size_t)(j + 4) * OUT_DIM];
        a5 += base[(size_t)(j + 5) * OUT_DIM];
        a6 += base[(size_t)(j + 6) * OUT_DIM];
        a7 += base[(size_t)(j + 7) * OUT_DIM];
    }
    for (; j < TOPK; j++) a0 += base[(size_t)j * OUT_DIM];
    out[b * OUT_DIM + c] = ((a0 + a1) + (a2 + a3)) + ((a4 + a5) + (a6 + a7));
}

// ------------------- launcher -------------------
extern "C" void kernel_launch(void* const* d_in, const int* in_sizes, int n_in,
                              void* d_out, int out_size) {
    const float* x     = (const float*)d_in[0];
    const float* gw    = (const float*)d_in[1];
    const float* gb    = (const float*)d_in[2];
    const float* tiles = (const float*)d_in[3];
    float* out = (float*)d_out;

    zero_kernel<<<1, 512>>>();
    router_kernel<<<BATCH / 4, 512>>>(x, gw, gb);
    cudaFuncSetAttribute(moe_gemm, cudaFuncAttributeMaxDynamicSharedMemorySize, SMEM_BYTES);
    moe_gemm<<<dim3(NWORK, 4, 2), 256, SMEM_BYTES>>>(x, tiles);
    reduce_kernel<<<BATCH * 2, 256>>>(out);
}

// round 17
// speedup vs baseline: 1.6463x; 1.6244x over previous
#include <cuda_runtime.h>
#include <cuda_fp16.h>
#include <cstdint>

#define BATCH    256
#define IN_DIM   512
#define OUT_DIM  512
#define NWORK    512
#define TOPK     154

// ------------------- persistent device scratch (no runtime allocation) -------------------
__device__ int   d_count[NWORK];                        // tokens per expert
__device__ int   d_tok[NWORK * 256];                    // token id per (expert, row)
__device__ float d_wt [NWORK * 256];                    // gate weight per (expert, row)
__device__ int   d_dst[NWORK * 256];                    // staging row (= b*TOPK + slot)
__device__ int   d_tokcnt[BATCH];                       // slot counter per token
__device__ float d_ystage[BATCH * TOPK * OUT_DIM];      // 77 MB staging: [token, slot, out]

// ------------------- helpers (baseline compute_103 PTX only) -------------------
__device__ __forceinline__ uint32_t smem_u32(const void* p) {
    uint32_t a;
    asm("{ .reg .u64 t; cvta.to.shared.u64 t, %1; cvt.u32.u64 %0, t; }" : "=r"(a) : "l"(p));
    return a;
}
#define SWZ(o) ((o) ^ (((o) >> 3) & 0x70))

__device__ __forceinline__ void ldm_x4(uint32_t* r, uint32_t addr) {
    asm volatile("ldmatrix.sync.aligned.m8n8.x4.shared.b16 {%0,%1,%2,%3}, [%4];"
                 : "=r"(r[0]), "=r"(r[1]), "=r"(r[2]), "=r"(r[3]) : "r"(addr));
}

__device__ __forceinline__ void mma_fp16(float* d, const uint32_t* a, const uint32_t* b) {
    asm volatile("mma.sync.aligned.m16n8k16.row.col.f32.f16.f16.f32 "
                 "{%0,%1,%2,%3}, {%4,%5,%6,%7}, {%8,%9}, {%0,%1,%2,%3};"
                 : "+f"(d[0]), "+f"(d[1]), "+f"(d[2]), "+f"(d[3])
                 : "r"(a[0]), "r"(a[1]), "r"(a[2]), "r"(a[3]), "r"(b[0]), "r"(b[1]));
}

__device__ __forceinline__ void sts128(uint32_t addr, uint4 v) {
    asm volatile("st.shared.v4.b32 [%0], {%1, %2, %3, %4};"
                 :: "r"(addr), "r"(v.x), "r"(v.y), "r"(v.z), "r"(v.w) : "memory");
}

__device__ __forceinline__ uint32_t pack_h2(float a, float b) {
    __half2 h = __floats2half2_rn(a, b);          // .x (low half) = a
    return *reinterpret_cast<uint32_t*>(&h);
}
__device__ __forceinline__ uint4 cvt8_single(float4 v0, float4 v1) {
    return make_uint4(pack_h2(v0.x, v0.y), pack_h2(v0.z, v0.w),
                      pack_h2(v1.x, v1.y), pack_h2(v1.z, v1.w));
}

// ------------------- kernel 0: zero counters -------------------
__global__ void zero_kernel() {
    int i = threadIdx.x;
    if (i < NWORK) d_count[i] = 0;
    if (i < BATCH) d_tokcnt[i] = 0;
}

// ------------------- kernel 1: router -------------------
__global__ void __launch_bounds__(512) router_kernel(const float* __restrict__ x,
                                                     const float* __restrict__ gw,
                                                     const float* __restrict__ gb) {
    __shared__ __align__(16) float sx[4][IN_DIM];
    __shared__ float sred[512];
    const int e  = threadIdx.x;
    const int b0 = blockIdx.x * 4;

    for (int i = e; i < 4 * IN_DIM; i += 512) sx[i >> 9][i & 511] = x[b0 * IN_DIM + i];
    __syncthreads();

    float bias = gb[e];
    float acc[4] = {bias, bias, bias, bias};
    const float4* g4 = (const float4*)(gw + (size_t)e * IN_DIM);
#pragma unroll 4
    for (int k = 0; k < IN_DIM / 4; k++) {
        float4 g = g4[k];
#pragma unroll
        for (int t = 0; t < 4; t++) {
            float4 xv = ((const float4*)sx[t])[k];
            acc[t] += g.x * xv.x + g.y * xv.y + g.z * xv.z + g.w * xv.w;
        }
    }

    for (int t = 0; t < 4; t++) {
        const int b = b0 + t;
        const float l = acc[t];
        uint32_t u = __float_as_uint(l);
        u = (u & 0x80000000u) ? ~u : (u | 0x80000000u);   // order-preserving map

        uint32_t res = 0;                                  // K-th largest threshold
        for (int bit = 31; bit >= 0; bit--) {
            uint32_t cand = res | (1u << bit);
            int c = __syncthreads_count(u >= cand);
            if (c >= TOPK) res = cand;
        }
        const bool sel = (u >= res);

        sred[e] = l;
        __syncthreads();
        for (int s = 256; s; s >>= 1) { if (e < s) sred[e] = fmaxf(sred[e], sred[e + s]); __syncthreads(); }
        const float lmax = sred[0];
        __syncthreads();

        const float ex = sel ? __expf(l - lmax) : 0.f;
        sred[e] = ex;
        __syncthreads();
        for (int s = 256; s; s >>= 1) { if (e < s) sred[e] += sred[e + s]; __syncthreads(); }
        const float wsum = sred[0];
        __syncthreads();

        if (sel) {
            float w = ex / wsum;
            int r = atomicAdd(&d_count[e], 1);
            int j = atomicAdd(&d_tokcnt[b], 1);
            if (r < 256 && j < TOPK) {
                d_tok[e * 256 + r] = b;
                d_wt [e * 256 + r] = w;
                d_dst[e * 256 + r] = b * TOPK + j;
            }
        }
        __syncthreads();
    }
}

// ------------------- kernel 2: grouped GEMM (R12 fill path + 4x2 warp grid) -------------------
// grid (expert 512, n-quarter 4, m-chunk 2), 256 thr, 2 CTAs/SM.
// Warp wid: m-strip (wid>>1)*32, n-half (wid&1)*64. A = x fp16; gate weight in epilogue.
// B prefetched to registers via LDG.128 at chunk top (R12 mechanism, proven fast).
#define SM_TOK   0
#define SM_WT    512
#define SM_DST   1024
#define SM_BUF   2048
#define BUF_SZ   32768           /* A 16K + B 16K fp16 */
#define A_OFF    0
#define B_OFF    16384
#define SMEM_BYTES (2048 + 2 * BUF_SZ)   /* 67584 B */

__global__ void __launch_bounds__(256, 2)
moe_gemm(const float* __restrict__ x, const float* __restrict__ tiles) {
    extern __shared__ char smem[];
    const int e  = blockIdx.x;
    const int nq = blockIdx.y;          // N-quarter: cols [nq*128, nq*128+128)
    const int mc = blockIdx.z;
    const int cnt  = d_count[e];
    const int rows = min(128, cnt - mc * 128);
    if (rows <= 0) return;

    const uint32_t sb  = smem_u32(smem);
    const int tid = threadIdx.x, wid = tid >> 5, lid = tid & 31;
    const int m0 = (wid >> 1) * 32;     // warp m-strip
    const int n0 = (wid & 1) * 64;      // warp n-half

    if (tid < 128) {
        int r = tid;
        bool valid = r < rows;
        int idx = e * 256 + mc * 128 + r;
        ((int*)  (smem + SM_TOK))[r] = valid ? d_tok[idx] : 0;
        ((float*)(smem + SM_WT ))[r] = valid ? d_wt [idx] : 0.f;
        ((int*)  (smem + SM_DST))[r] = valid ? d_dst[idx] : 0;
    }
    __syncthreads();

    // ldmatrix lane address components (validated R10-R15)
    const int ar  = (lid & 7) + ((lid >> 3) & 1) * 8;   // A: row within 16-tile
    const int akb = ((lid >> 4) & 1) * 16;              // A: k-byte offset
    const int br  = (lid & 7) + ((lid >> 4) & 1) * 8;   // B: n within 16-group
    const int bkb = ((lid >> 3) & 1) * 16;              // B: k-byte offset

    float acc[2][8][4];
#pragma unroll
    for (int mt = 0; mt < 2; mt++)
#pragma unroll
        for (int t = 0; t < 8; t++)
#pragma unroll
            for (int j = 0; j < 4; j++) acc[mt][t][j] = 0.f;

    const float* tbase = tiles + ((size_t)e * OUT_DIM + nq * 128) * IN_DIM;
    const int fr = tid >> 3, fg = tid & 7;              // fill role: row 0..31, 8-col group

    float4 pf[8];                                        // B prefetch registers

    // ---- B: issue 8 LDG.128 for chunk kc into pf (rows fr, fr+32, fr+64, fr+96) ----
    auto loadB = [&](int kc) {
#pragma unroll
        for (int it = 0; it < 4; it++) {
            const float4* p = (const float4*)(tbase + (size_t)(fr + 32 * it) * IN_DIM + kc * 64 + fg * 8);
            pf[2 * it]     = p[0];
            pf[2 * it + 1] = p[1];
        }
    };
    // ---- B: convert prefetched regs into buffer ----
    auto storeB = [&](uint32_t bufb) {
#pragma unroll
        for (int it = 0; it < 4; it++) {
            uint32_t off = SWZ((uint32_t)((fr + 32 * it) * 128 + fg * 16));
            sts128(bufb + B_OFF + off, cvt8_single(pf[2 * it], pf[2 * it + 1]));
        }
    };
    // ---- A: gather + convert + store (x is L2-resident) ----
    auto fillA = [&](int kc, uint32_t bufb) {
#pragma unroll
        for (int it = 0; it < 4; it++) {
            int r = fr + 32 * it;
            int tok = ((int*)(smem + SM_TOK))[r];
            const float4* p = (const float4*)(x + (size_t)tok * IN_DIM + kc * 64 + fg * 8);
            float4 v0 = p[0], v1 = p[1];
            uint32_t off = SWZ((uint32_t)(r * 128 + fg * 16));
            sts128(bufb + A_OFF + off, cvt8_single(v0, v1));
        }
    };

    // prologue: stage chunk 0
    loadB(0);
    storeB(sb + SM_BUF);
    fillA(0, sb + SM_BUF);
    __syncthreads();

    for (int kc = 0; kc < 8; kc++) {
        const uint32_t cur = sb + SM_BUF + (uint32_t)(kc & 1) * BUF_SZ;

        if (kc < 7) loadB(kc + 1);             // DRAM LDGs in flight across the MMA phase

        if (m0 < rows) {                       // M-skip (32-row strips)
#pragma unroll
            for (int ks = 0; ks < 4; ks++) {
                uint32_t a0[4], a1[4];
                ldm_x4(a0, cur + A_OFF + SWZ((uint32_t)((m0 + ar) * 128 + 32 * ks + akb)));
                ldm_x4(a1, cur + A_OFF + SWZ((uint32_t)((m0 + 16 + ar) * 128 + 32 * ks + akb)));
#pragma unroll
                for (int np = 0; np < 4; np++) {
                    uint32_t b[4];
                    ldm_x4(b, cur + B_OFF + SWZ((uint32_t)((n0 + np * 16 + br) * 128 + 32 * ks + bkb)));
                    mma_fp16(acc[0][2 * np],     a0, b);
                    mma_fp16(acc[1][2 * np],     a1, b);
                    mma_fp16(acc[0][2 * np + 1], a0, b + 2);
                    mma_fp16(acc[1][2 * np + 1], a1, b + 2);
                }
            }
        }

        if (kc < 7) {
            const uint32_t nxt = sb + SM_BUF + (uint32_t)((kc + 1) & 1) * BUF_SZ;
            storeB(nxt);
            fillA(kc + 1, nxt);
            __syncthreads();                   // one barrier per chunk
        }
    }

    // epilogue: rows m0+16*mt+lid/4 (+8); cols n0 + t*8 + 2*(lid&3); apply gate weight
    if (m0 < rows) {
#pragma unroll
        for (int mt = 0; mt < 2; mt++) {
            const int mA = m0 + 16 * mt + (lid >> 2);
            const int mB = mA + 8;
            const bool vA = mA < rows, vB = mB < rows;
            const int dA = vA ? ((int*)(smem + SM_DST))[mA] : 0;
            const int dB = vB ? ((int*)(smem + SM_DST))[mB] : 0;
            const float wA = vA ? ((float*)(smem + SM_WT))[mA] : 0.f;
            const float wB = vB ? ((float*)(smem + SM_WT))[mB] : 0.f;
            float* oA = d_ystage + (size_t)dA * OUT_DIM + nq * 128 + n0;
            float* oB = d_ystage + (size_t)dB * OUT_DIM + nq * 128 + n0;
            const int nb = 2 * (lid & 3);
#pragma unroll
            for (int t = 0; t < 8; t++) {
                int n = t * 8 + nb;
                if (vA) *(float2*)(oA + n) = make_float2(wA * acc[mt][t][0], wA * acc[mt][t][1]);
                if (vB) *(float2*)(oB + n) = make_float2(wB * acc[mt][t][2], wB * acc[mt][t][3]);
            }
        }
    }
}

// ------------------- kernel 3: per-token reduction over 154 staged rows -------------------
__global__ void __launch_bounds__(256) reduce_kernel(float* __restrict__ out) {
    const int b    = blockIdx.x >> 1;
    const int half = blockIdx.x & 1;
    const int c    = half * 256 + threadIdx.x;
    const float* base = d_ystage + (size_t)b * TOPK * OUT_DIM + c;
    float a0 = 0.f, a1 = 0.f, a2 = 0.f, a3 = 0.f;
    float a4 = 0.f, a5 = 0.f, a6 = 0.f, a7 = 0.f;
    int j = 0;
    for (; j + 8 <= TOPK; j += 8) {            // 8-way MLP
        a0 += base[(size_t)(j + 0) * OUT_DIM];
        a1 += base[(size_t)(j + 1) * OUT_DIM];
        a2 += base[(size_t)(j + 2) * OUT_DIM];
        a3 += base[(size_t)(j + 3) * OUT_DIM];
        a4 += base[(size_t)(j + 4) * OUT_DIM];
        a5 += base[(size_t)(j + 5) * OUT_DIM];
        a6 += base[(size_t)(j + 6) * OUT_DIM];
        a7 += base[(size_t)(j + 7) * OUT_DIM];
    }
    for (; j < TOPK; j++) a0 += base[(size_t)j * OUT_DIM];
    out[b * OUT_DIM + c] = ((a0 + a1) + (a2 + a3)) + ((a4 + a5) + (a6 + a7));
}

// ------------------- launcher -------------------
extern "C" void kernel_launch(void* const* d_in, const int* in_sizes, int n_in,
                              void* d_out, int out_size) {
    const float* x     = (const float*)d_in[0];
    const float* gw    = (const float*)d_in[1];
    const float* gb    = (const float*)d_in[2];
    const float* tiles = (const float*)d_in[3];
    float* out = (float*)d_out;

    zero_kernel<<<1, 512>>>();
    router_kernel<<<BATCH / 4, 512>>>(x, gw, gb);
    cudaFuncSetAttribute(moe_gemm, cudaFuncAttributeMaxDynamicSharedMemorySize, SMEM_BYTES);
    moe_gemm<<<dim3(NWORK, 4, 2), 256, SMEM_BYTES>>>(x, tiles);
    reduce_kernel<<<BATCH * 2, 256>>>(out);
}